// round 15
// baseline (speedup 1.0000x reference)
#include <cuda_runtime.h>
#include <cuda_bf16.h>
#include <cstdint>
#include <math.h>

// ---------------- Problem constants ----------------
#define BB   256
#define NH   850
#define TT   70
#define PK   896            // padded K for states (14*64)
#define PK0  1792           // padded K for [x, h]  (28*64)
#define NKT_E 14            // K sub-stages, edge GEMM
#define NKT_0 28            // K sub-stages stored for W0 (x: 0..13, h: 14..27)
#define NTIL_N 27           // N pair-tiles of 32
#define BLK_HALFS 4096      // one packed B block: 64k x 64cols bf16 = 8KB

#define A_SLOT_BYTES (32 * 72 * 2)                          // 4608
#define A_RING4_BYTES (4 * A_SLOT_BYTES)                    // 18432
#define SMEM_GEMM (A_RING4_BYTES + 4 * BLK_HALFS * 2)       // 51200
#define SMEM_LVL4 (A_RING4_BYTES + 4 * 2 * BLK_HALFS * 2)   // 83968

// ---------------- Global scratch (static; no allocs) ----------------
__device__ __align__(16) float         g_statesF[9][BB * PK];  // fp32 residual/mean
__device__ __align__(16) __nv_bfloat16 g_statesB[9][BB * PK];  // bf16 GEMM A operand
__device__ __align__(16) __nv_bfloat16 g_xh[BB * PK0];         // bf16 (h half used @896)
__device__ __align__(16) float         g_hfp[BB * NH];         // fp32 h_prev
__device__ __align__(16) __nv_bfloat16 g_xall[(size_t)TT * BB * PK]; // bf16 x, all steps
__device__ __align__(16) float         g_xpc[BB * 864];        // x@W0 partial, c half
__device__ __align__(16) float         g_xph[BB * 864];        // x@W0 partial, h half
__device__ __align__(16) __nv_bfloat16 g_w0t[(size_t)NTIL_N * NKT_0 * BLK_HALFS];
__device__ __align__(16) __nv_bfloat16 g_wet[8][(size_t)NTIL_N * NKT_E * BLK_HALFS];

struct Edge { int pred, out, w, act; };
__constant__ Edge c_edges[8] = {
    {0, 1, 0, 0}, {1, 2, 1, 1}, {1, 3, 2, 1}, {1, 4, 3, 3},
    {2, 5, 4, 0}, {5, 6, 5, 2}, {3, 7, 6, 0}, {5, 8, 7, 1},
};

// ---------------- Helpers ----------------
__device__ __forceinline__ void cp16(void* dst, const void* src) {
    uint32_t d = (uint32_t)__cvta_generic_to_shared(dst);
    asm volatile("cp.async.cg.shared.global [%0], [%1], 16;" :: "r"(d), "l"(src) : "memory");
}
__device__ __forceinline__ void cp_commit() {
    asm volatile("cp.async.commit_group;" ::: "memory");
}
template <int N> __device__ __forceinline__ void cp_wait() {
    asm volatile("cp.async.wait_group %0;" :: "n"(N) : "memory");
}
__device__ __forceinline__ void ldsm4(uint32_t* a, uint32_t addr) {
    asm volatile("ldmatrix.sync.aligned.m8n8.x4.shared.b16 {%0,%1,%2,%3}, [%4];"
        : "=r"(a[0]), "=r"(a[1]), "=r"(a[2]), "=r"(a[3]) : "r"(addr));
}
__device__ __forceinline__ void mma16(float* d, const uint32_t* a, uint32_t b0, uint32_t b1) {
    asm volatile("mma.sync.aligned.m16n8k16.row.col.f32.bf16.bf16.f32 "
        "{%0,%1,%2,%3}, {%4,%5,%6,%7}, {%8,%9}, {%0,%1,%2,%3};"
        : "+f"(d[0]), "+f"(d[1]), "+f"(d[2]), "+f"(d[3])
        : "r"(a[0]), "r"(a[1]), "r"(a[2]), "r"(a[3]), "r"(b0), "r"(b1));
}
__device__ __forceinline__ float actf(float x, int a) {
    if (a == 0) return tanhf(x);
    if (a == 1) return fmaxf(x, 0.f);
    if (a == 2) return 1.f / (1.f + __expf(-x));
    return x;
}
__device__ __forceinline__ float sigf(float x) { return 1.f / (1.f + __expf(-x)); }

// ---------------- GEMM mainloop (R12 4-slot ring; arithmetic unchanged) ----------
// Accumulates cacc/hacc over nsub K-sub-stages. Epilogue handled by caller.
__device__ __forceinline__ void gemm_main(
    __nv_bfloat16 (*As)[32][72], __nv_bfloat16 (*Bs)[BLK_HALFS],
    const __nv_bfloat16* __restrict__ A, int strideA,
    const __nv_bfloat16* __restrict__ Wblk,
    int nsub, int m0, float* cacc, float* hacc)
{
    const int tid = threadIdx.x, wid = tid >> 5, lid = tid & 31;
    const int wm = wid & 1, wn = wid >> 1;

    auto loadsub = [&](int slot, int kt) {
        {
            int r = tid >> 3, c = tid & 7;
            cp16(&As[slot][r][c * 8], A + (size_t)(m0 + r) * strideA + kt * 64 + c * 8);
        }
        const __nv_bfloat16* wb = Wblk + (size_t)kt * BLK_HALFS;
        #pragma unroll
        for (int i = 0; i < 2; i++) {
            int idx = tid + i * 256;
            cp16(&Bs[slot][idx * 8], wb + idx * 8);
        }
    };

    loadsub(0, 0);
    loadsub(1, 1);
    cp_commit();

    const int niter = nsub >> 1;
    for (int it = 0; it < niter; it++) {
        if (it + 1 < niter) {
            const int k2 = 2 * it + 2;
            loadsub(k2 & 3, k2);
            loadsub((k2 + 1) & 3, k2 + 1);
            cp_commit();
            cp_wait<1>();
        } else {
            cp_wait<0>();
        }
        __syncthreads();

        #pragma unroll
        for (int half = 0; half < 2; half++) {
            const int slot = (2 * it + half) & 3;
            const uint32_t abase = (uint32_t)__cvta_generic_to_shared(&As[slot][0][0]);
            const uint32_t arow = abase + (uint32_t)(wm * 16 + (lid & 15)) * 144
                                        + (uint32_t)(lid >> 4) * 16;
            const __nv_bfloat16* bb = &Bs[slot][0];
            #pragma unroll
            for (int ks = 0; ks < 4; ks++) {
                uint32_t a0[4];
                ldsm4(a0, arow + ks * 32);
                const uint2 bc = *(const uint2*)(bb + ((ks * 8 + wn) * 32 + lid) * 4);
                const uint2 bh = *(const uint2*)(bb + ((ks * 8 + wn) * 32 + lid) * 4 + 512);
                mma16(cacc, a0, bc.x, bc.y);
                mma16(hacc, a0, bh.x, bh.y);
            }
        }
        __syncthreads();
    }
}

// Highway epilogue (shared). ADD_PARTIAL adds precomputed x@W0 partials first.
template <bool ADD_PARTIAL>
__device__ __forceinline__ void highway_epi(
    const float* cacc, const float* hacc,
    const float* __restrict__ P, int strideP,
    float* __restrict__ OutF, __nv_bfloat16* __restrict__ OutB,
    int act, int m0, int j0)
{
    const int tid = threadIdx.x, wid = tid >> 5, lid = tid & 31;
    const int wm = wid & 1, wn = wid >> 1;
    const int lr = lid >> 2, lc = lid & 3;
    const int r0 = m0 + wm * 16 + lr;
    const int c0 = j0 + wn * 8 + lc * 2;
    #pragma unroll
    for (int e = 0; e < 4; e++) {
        int r = r0 + (e >> 1) * 8;
        int c = c0 + (e & 1);
        if (c < NH) {
            float cv = cacc[e], hv = hacc[e];
            if (ADD_PARTIAL) {
                cv += g_xpc[(size_t)r * 864 + c];
                hv += g_xph[(size_t)r * 864 + c];
            }
            float sp = P[(size_t)r * strideP + c];
            float g  = sigf(cv);
            float av = actf(hv, act);
            float v  = sp + g * (av - sp);
            OutF[(size_t)r * PK + c] = v;
            OutB[(size_t)r * PK + c] = __float2bfloat16_rn(v);
        }
    }
}

// x@W0 partial body: raw accumulator write (no activation)
__device__ __forceinline__ void xpart_body(int t) {
    extern __shared__ char smem[];
    auto As = reinterpret_cast<__nv_bfloat16 (*)[32][72]>(smem);
    auto Bs = reinterpret_cast<__nv_bfloat16 (*)[BLK_HALFS]>(smem + A_RING4_BYTES);
    const int nt = blockIdx.x, m0 = blockIdx.y * 32, j0 = nt * 32;

    float cacc[4] = {}, hacc[4] = {};
    gemm_main(As, Bs, g_xall + (size_t)t * BB * PK, PK,
              g_w0t + (size_t)nt * NKT_0 * BLK_HALFS,   // kt 0..13 = x rows
              NKT_E, m0, cacc, hacc);

    const int tid = threadIdx.x, wid = tid >> 5, lid = tid & 31;
    const int wm = wid & 1, wn = wid >> 1;
    const int lr = lid >> 2, lc = lid & 3;
    const int r0 = m0 + wm * 16 + lr;
    const int c0 = j0 + wn * 8 + lc * 2;
    #pragma unroll
    for (int e = 0; e < 4; e++) {
        int r = r0 + (e >> 1) * 8;
        int c = c0 + (e & 1);
        if (c < NH) {
            g_xpc[(size_t)r * 864 + c] = cacc[e];
            g_xph[(size_t)r * 864 + c] = hacc[e];
        }
    }
}

__device__ __forceinline__ void edge_body(int e) {
    extern __shared__ char smem[];
    auto As = reinterpret_cast<__nv_bfloat16 (*)[32][72]>(smem);
    auto Bs = reinterpret_cast<__nv_bfloat16 (*)[BLK_HALFS]>(smem + A_RING4_BYTES);
    const int nt = blockIdx.x, m0 = blockIdx.y * 32, j0 = nt * 32;
    Edge E = c_edges[e];
    float cacc[4] = {}, hacc[4] = {};
    gemm_main(As, Bs, g_statesB[E.pred], PK,
              g_wet[E.w] + (size_t)nt * NKT_E * BLK_HALFS, NKT_E, m0, cacc, hacc);
    highway_epi<false>(cacc, hacc, g_statesF[E.pred], PK,
                       g_statesF[E.out], g_statesB[E.out], E.act, m0, j0);
}

// ---------------- Kernels ----------------
// gemm0h: s0 = highway(x@W0 (precomputed) + h@W0_h), K = 896
__global__ __launch_bounds__(256) void gemm0h_kernel() {
    extern __shared__ char smem[];
    auto As = reinterpret_cast<__nv_bfloat16 (*)[32][72]>(smem);
    auto Bs = reinterpret_cast<__nv_bfloat16 (*)[BLK_HALFS]>(smem + A_RING4_BYTES);
    const int nt = blockIdx.x, m0 = blockIdx.y * 32, j0 = nt * 32;
    float cacc[4] = {}, hacc[4] = {};
    gemm_main(As, Bs, g_xh + PK, PK0,
              g_w0t + (size_t)nt * NKT_0 * BLK_HALFS + (size_t)NKT_E * BLK_HALFS,  // kt 14..27
              NKT_E, m0, cacc, hacc);
    highway_epi<true>(cacc, hacc, g_hfp, NH, g_statesF[0], g_statesB[0], 0, m0, j0);
}

// L1 fused: z=0 -> edge0; z=1 -> xpart(t+1) on the otherwise-idle half of the chip
__global__ __launch_bounds__(256) void l1_kernel(int tnext) {
    if (blockIdx.z == 0) edge_body(0);
    else if (tnext < TT) xpart_body(tnext);
}
__global__ __launch_bounds__(256) void edge_kernel(int e0, int e1, int e2) {
    int e = (blockIdx.z == 0) ? e0 : ((blockIdx.z == 1) ? e1 : e2);
    edge_body(e);
}
__global__ __launch_bounds__(256) void xpart_kernel(int t) { xpart_body(t); }

// ---------------- Fused level-4: e5 + e7 from s5, + mean + staging (R12 version) ----
__global__ __launch_bounds__(256) void lvl4_kernel(float* __restrict__ out, int t)
{
    extern __shared__ char smem[];
    auto As = reinterpret_cast<__nv_bfloat16 (*)[32][72]>(smem);
    auto Bs = reinterpret_cast<__nv_bfloat16 (*)[2][BLK_HALFS]>(smem + A_RING4_BYTES);

    const int tid = threadIdx.x, wid = tid >> 5, lid = tid & 31;
    const int wm = wid & 1, wn = wid >> 1;
    const int lr = lid >> 2, lc = lid & 3;
    const int nt = blockIdx.x, m0 = blockIdx.y * 32, j0 = nt * 32;

    const __nv_bfloat16* A  = g_statesB[5];
    const __nv_bfloat16* W5 = g_wet[5] + (size_t)nt * NKT_E * BLK_HALFS;
    const __nv_bfloat16* W7 = g_wet[7] + (size_t)nt * NKT_E * BLK_HALFS;

    float c5a[4] = {}, h5a[4] = {}, c7a[4] = {}, h7a[4] = {};

    auto loadsub = [&](int slot, int kt) {
        {
            int r = tid >> 3, c = tid & 7;
            cp16(&As[slot][r][c * 8], A + (size_t)(m0 + r) * PK + kt * 64 + c * 8);
        }
        #pragma unroll
        for (int i = 0; i < 2; i++) {
            int idx = tid + i * 256;
            cp16(&Bs[slot][0][idx * 8], W5 + (size_t)kt * BLK_HALFS + idx * 8);
            cp16(&Bs[slot][1][idx * 8], W7 + (size_t)kt * BLK_HALFS + idx * 8);
        }
    };

    loadsub(0, 0);
    loadsub(1, 1);
    cp_commit();

    const int niter = NKT_E >> 1;
    for (int it = 0; it < niter; it++) {
        if (it + 1 < niter) {
            const int k2 = 2 * it + 2;
            loadsub(k2 & 3, k2);
            loadsub((k2 + 1) & 3, k2 + 1);
            cp_commit();
            cp_wait<1>();
        } else {
            cp_wait<0>();
        }
        __syncthreads();

        #pragma unroll
        for (int half = 0; half < 2; half++) {
            const int slot = (2 * it + half) & 3;
            const uint32_t abase = (uint32_t)__cvta_generic_to_shared(&As[slot][0][0]);
            const uint32_t arow = abase + (uint32_t)(wm * 16 + (lid & 15)) * 144
                                        + (uint32_t)(lid >> 4) * 16;
            const __nv_bfloat16* b5 = &Bs[slot][0][0];
            const __nv_bfloat16* b7 = &Bs[slot][1][0];
            #pragma unroll
            for (int ks = 0; ks < 4; ks++) {
                uint32_t a0[4];
                ldsm4(a0, arow + ks * 32);
                const int boff = ((ks * 8 + wn) * 32 + lid) * 4;
                const uint2 bc5 = *(const uint2*)(b5 + boff);
                const uint2 bh5 = *(const uint2*)(b5 + boff + 512);
                const uint2 bc7 = *(const uint2*)(b7 + boff);
                const uint2 bh7 = *(const uint2*)(b7 + boff + 512);
                mma16(c5a, a0, bc5.x, bc5.y);
                mma16(h5a, a0, bh5.x, bh5.y);
                mma16(c7a, a0, bc7.x, bc7.y);
                mma16(h7a, a0, bh7.x, bh7.y);
            }
        }
        __syncthreads();
    }

    // epilogue: s6/s8 in registers, mean in original s1..s8 order, stage h
    const int r0 = m0 + wm * 16 + lr;
    const int c0 = j0 + wn * 8 + lc * 2;
    #pragma unroll
    for (int e = 0; e < 4; e++) {
        int r = r0 + (e >> 1) * 8;
        int c = c0 + (e & 1);
        if (c < NH) {
            float sp = g_statesF[5][(size_t)r * PK + c];
            float v6 = sp + sigf(c5a[e]) * (sigf(h5a[e]) - sp);          // edge5: sigmoid
            float v8 = sp + sigf(c7a[e]) * (fmaxf(h7a[e], 0.f) - sp);    // edge7: relu
            float s = 0.f;
            s += g_statesF[1][(size_t)r * PK + c];
            s += g_statesF[2][(size_t)r * PK + c];
            s += g_statesF[3][(size_t)r * PK + c];
            s += g_statesF[4][(size_t)r * PK + c];
            s += sp;        // s5
            s += v6;        // s6
            s += g_statesF[7][(size_t)r * PK + c];
            s += v8;        // s8
            s *= 0.125f;
            const size_t oi = (size_t)r * NH + c;
            out[(size_t)t * (BB * NH) + oi] = s;
            g_hfp[oi] = s;
            g_xh[(size_t)r * PK0 + PK + c] = __float2bfloat16_rn(s);
            if (t + 1 >= TT)
                out[(size_t)TT * (BB * NH) + oi] = s;    // hiddens[-1]
        }
    }
}

// ---------------- Initial staging ----------------
__global__ void stage0_kernel(const float* __restrict__ h0) {
    int i = blockIdx.x * blockDim.x + threadIdx.x;
    if (i < BB * NH) {
        int b = i / NH, j = i % NH;
        g_xh[b * PK0 + PK + j] = __float2bfloat16_rn(h0[i]);
        g_hfp[i] = h0[i];
    }
}
// Stage ALL x inputs to padded bf16 (one-time)
__global__ void prep_xall(const float* __restrict__ inputs) {
    size_t i = (size_t)blockIdx.x * blockDim.x + threadIdx.x;
    if (i >= (size_t)TT * BB * PK) return;
    int j = (int)(i % PK);
    size_t tb = i / PK;            // t*BB + b
    float v = (j < NH) ? inputs[tb * NH + j] : 0.f;
    g_xall[i] = __float2bfloat16_rn(v);
}

// ---------------- Weight prep: packed B fragment blocks (unchanged layout) ----------------
__global__ void prep_w0(const float* __restrict__ W0) {
    size_t i = (size_t)blockIdx.x * blockDim.x + threadIdx.x;
    if (i >= (size_t)NTIL_N * NKT_0 * BLK_HALFS) return;
    int blk = (int)(i >> 12), pos = (int)(i & 4095);
    int nt = blk / NKT_0, kt = blk % NKT_0;
    int hh = pos & 1, rr = (pos >> 1) & 1, lane = (pos >> 2) & 31;
    int g = (pos >> 7) & 7, ks = (pos >> 10) & 3;
    int lcc = lane & 3, lrr = lane >> 2;
    int p = kt * 64 + ks * 16 + 2 * lcc + 8 * rr + hh;
    int kr = (p < NH) ? p : ((p >= PK && p < PK + NH) ? (NH + p - PK) : -1);
    int jj = nt * 32 + (g & 3) * 8 + lrr;
    float v = 0.f;
    if (kr >= 0 && jj < NH) {
        int wc = (g < 4) ? jj : NH + jj;
        v = W0[(size_t)kr * (2 * NH) + wc];
    }
    g_w0t[i] = __float2bfloat16_rn(v);
}
__global__ void prep_we(const float* __restrict__ Ws) {
    size_t i = (size_t)blockIdx.x * blockDim.x + threadIdx.x;
    if (i >= (size_t)8 * NTIL_N * NKT_E * BLK_HALFS) return;
    int e = (int)(i / ((size_t)NTIL_N * NKT_E * BLK_HALFS));
    size_t rm = i % ((size_t)NTIL_N * NKT_E * BLK_HALFS);
    int blk = (int)(rm >> 12), pos = (int)(rm & 4095);
    int nt = blk / NKT_E, kt = blk % NKT_E;
    int hh = pos & 1, rr = (pos >> 1) & 1, lane = (pos >> 2) & 31;
    int g = (pos >> 7) & 7, ks = (pos >> 10) & 3;
    int lcc = lane & 3, lrr = lane >> 2;
    int p = kt * 64 + ks * 16 + 2 * lcc + 8 * rr + hh;
    int jj = nt * 32 + (g & 3) * 8 + lrr;
    float v = 0.f;
    if (p < NH && jj < NH) {
        int wc = (g < 4) ? jj : NH + jj;
        v = Ws[((size_t)e * NH + p) * (2 * NH) + wc];
    }
    g_wet[e][rm] = __float2bfloat16_rn(v);
}

// ---------------- Zero bf16 padding ----------------
__global__ void zero_kernel() {
    int i = blockIdx.x * blockDim.x + threadIdx.x;
    if (i < 9 * BB * PK) (&g_statesB[0][0])[i] = __float2bfloat16_rn(0.f);
    if (i < BB * PK0)    g_xh[i] = __float2bfloat16_rn(0.f);
}

// ---------------- Host ----------------
extern "C" void kernel_launch(void* const* d_in, const int* in_sizes, int n_in,
                              void* d_out, int out_size)
{
    const float* inputs = (const float*)d_in[0];  // [T, B, NH]
    const float* hidden = (const float*)d_in[1];  // [1, B, NH]
    const float* W0     = (const float*)d_in[2];  // [2*NH, 2*NH]
    const float* Ws     = (const float*)d_in[3];  // [8, NH, 2*NH]
    float* out = (float*)d_out;

    cudaFuncSetAttribute(gemm0h_kernel, cudaFuncAttributeMaxDynamicSharedMemorySize, SMEM_GEMM);
    cudaFuncSetAttribute(l1_kernel,     cudaFuncAttributeMaxDynamicSharedMemorySize, SMEM_GEMM);
    cudaFuncSetAttribute(edge_kernel,   cudaFuncAttributeMaxDynamicSharedMemorySize, SMEM_GEMM);
    cudaFuncSetAttribute(xpart_kernel,  cudaFuncAttributeMaxDynamicSharedMemorySize, SMEM_GEMM);
    cudaFuncSetAttribute(lvl4_kernel,   cudaFuncAttributeMaxDynamicSharedMemorySize, SMEM_LVL4);

    zero_kernel<<<(9 * BB * PK + 255) / 256, 256>>>();
    prep_w0<<<(int)(((size_t)NTIL_N * NKT_0 * BLK_HALFS + 255) / 256), 256>>>(W0);
    prep_we<<<(int)(((size_t)8 * NTIL_N * NKT_E * BLK_HALFS + 255) / 256), 256>>>(Ws);
    prep_xall<<<(int)(((size_t)TT * BB * PK + 255) / 256), 256>>>(inputs);
    stage0_kernel<<<(BB * NH + 255) / 256, 256>>>(hidden);
    xpart_kernel<<<dim3(NTIL_N, 8, 1), 256, SMEM_GEMM>>>(0);   // x-partial for step 0

    const dim3 blk(256);
    for (int t = 0; t < TT; t++) {
        gemm0h_kernel<<<dim3(NTIL_N, 8, 1), blk, SMEM_GEMM>>>();              // K=896 now
        l1_kernel<<<dim3(NTIL_N, 8, 2), blk, SMEM_GEMM>>>(t + 1);             // e0 + xpart(t+1)
        edge_kernel<<<dim3(NTIL_N, 8, 3), blk, SMEM_GEMM>>>(1, 2, 3);         // L2
        edge_kernel<<<dim3(NTIL_N, 8, 2), blk, SMEM_GEMM>>>(4, 6, 0);         // L3
        lvl4_kernel<<<dim3(NTIL_N, 8, 1), blk, SMEM_LVL4>>>(out, t);          // L4 + mean + staging
    }
}

// round 16
// speedup vs baseline: 1.4374x; 1.4374x over previous
#include <cuda_runtime.h>
#include <cuda_bf16.h>
#include <cstdint>
#include <math.h>

// ---------------- Problem constants ----------------
#define BB   256
#define NH   850
#define TT   70
#define PK   896            // padded K for states (14*64)
#define PK0  1792           // padded K for [x, h]  (28*64)
#define NKT_E 14            // K sub-stages, edge GEMM
#define NKT_0 28            // K sub-stages, init GEMM
#define NTIL_N 27           // N pair-tiles of 32
#define BLK_HALFS 4096      // one packed B block: 64k x 64cols bf16 = 8KB

#define A_SLOT_BYTES (32 * 72 * 2)                          // 4608
#define A_RING4_BYTES (4 * A_SLOT_BYTES)                    // 18432
#define SMEM_GEMM (A_RING4_BYTES + 4 * BLK_HALFS * 2)       // 51200
#define SMEM_LVL4 (A_RING4_BYTES + 4 * 2 * BLK_HALFS * 2)   // 83968
#define SMEM_LVL2 (3 * A_SLOT_BYTES + 3 * 3 * BLK_HALFS * 2) // 87552

// ---------------- Global scratch (static; no allocs) ----------------
__device__ __align__(16) float         g_statesF[9][BB * PK];  // fp32 residual/mean
__device__ __align__(16) __nv_bfloat16 g_statesB[9][BB * PK];  // bf16 GEMM A operand
__device__ __align__(16) __nv_bfloat16 g_xh[BB * PK0];         // bf16 [x | h]
__device__ __align__(16) float         g_hfp[BB * NH];         // fp32 h_prev
__device__ __align__(16) __nv_bfloat16 g_w0t[(size_t)NTIL_N * NKT_0 * BLK_HALFS];
__device__ __align__(16) __nv_bfloat16 g_wet[8][(size_t)NTIL_N * NKT_E * BLK_HALFS];

struct Edge { int pred, out, w, act; };
__constant__ Edge c_edges[8] = {
    {0, 1, 0, 0}, {1, 2, 1, 1}, {1, 3, 2, 1}, {1, 4, 3, 3},
    {2, 5, 4, 0}, {5, 6, 5, 2}, {3, 7, 6, 0}, {5, 8, 7, 1},
};

// ---------------- Helpers ----------------
__device__ __forceinline__ void cp16(void* dst, const void* src) {
    uint32_t d = (uint32_t)__cvta_generic_to_shared(dst);
    asm volatile("cp.async.cg.shared.global [%0], [%1], 16;" :: "r"(d), "l"(src) : "memory");
}
__device__ __forceinline__ void cp_commit() {
    asm volatile("cp.async.commit_group;" ::: "memory");
}
template <int N> __device__ __forceinline__ void cp_wait() {
    asm volatile("cp.async.wait_group %0;" :: "n"(N) : "memory");
}
__device__ __forceinline__ void ldsm4(uint32_t* a, uint32_t addr) {
    asm volatile("ldmatrix.sync.aligned.m8n8.x4.shared.b16 {%0,%1,%2,%3}, [%4];"
        : "=r"(a[0]), "=r"(a[1]), "=r"(a[2]), "=r"(a[3]) : "r"(addr));
}
__device__ __forceinline__ void mma16(float* d, const uint32_t* a, uint32_t b0, uint32_t b1) {
    asm volatile("mma.sync.aligned.m16n8k16.row.col.f32.bf16.bf16.f32 "
        "{%0,%1,%2,%3}, {%4,%5,%6,%7}, {%8,%9}, {%0,%1,%2,%3};"
        : "+f"(d[0]), "+f"(d[1]), "+f"(d[2]), "+f"(d[3])
        : "r"(a[0]), "r"(a[1]), "r"(a[2]), "r"(a[3]), "r"(b0), "r"(b1));
}
__device__ __forceinline__ float actf(float x, int a) {
    if (a == 0) return tanhf(x);
    if (a == 1) return fmaxf(x, 0.f);
    if (a == 2) return 1.f / (1.f + __expf(-x));
    return x;
}
__device__ __forceinline__ float sigf(float x) { return 1.f / (1.f + __expf(-x)); }

// ---------------- GEMM core: tile 32 rows x 32 col-pairs (R12, unchanged) ----------
__device__ __forceinline__ void gemm_core32(
    __nv_bfloat16 (*As)[32][72], __nv_bfloat16 (*Bs)[BLK_HALFS],
    const __nv_bfloat16* __restrict__ A, int strideA,
    const __nv_bfloat16* __restrict__ Wblk,
    const float* __restrict__ P, int strideP,
    float* __restrict__ OutF, __nv_bfloat16* __restrict__ OutB,
    int act, int nsub, int m0, int j0)
{
    const int tid = threadIdx.x, wid = tid >> 5, lid = tid & 31;
    const int wm = wid & 1, wn = wid >> 1;    // 2 x 4 warp grid
    const int lr = lid >> 2, lc = lid & 3;

    float cacc[4] = {}, hacc[4] = {};

    auto loadsub = [&](int slot, int kt) {
        {
            int r = tid >> 3, c = tid & 7;
            cp16(&As[slot][r][c * 8], A + (size_t)(m0 + r) * strideA + kt * 64 + c * 8);
        }
        const __nv_bfloat16* wb = Wblk + (size_t)kt * BLK_HALFS;
        #pragma unroll
        for (int i = 0; i < 2; i++) {
            int idx = tid + i * 256;
            cp16(&Bs[slot][idx * 8], wb + idx * 8);
        }
    };

    loadsub(0, 0);
    loadsub(1, 1);
    cp_commit();

    const int niter = nsub >> 1;
    for (int it = 0; it < niter; it++) {
        if (it + 1 < niter) {
            const int k2 = 2 * it + 2;
            loadsub(k2 & 3, k2);
            loadsub((k2 + 1) & 3, k2 + 1);
            cp_commit();
            cp_wait<1>();
        } else {
            cp_wait<0>();
        }
        __syncthreads();

        #pragma unroll
        for (int half = 0; half < 2; half++) {
            const int slot = (2 * it + half) & 3;
            const uint32_t abase = (uint32_t)__cvta_generic_to_shared(&As[slot][0][0]);
            const uint32_t arow = abase + (uint32_t)(wm * 16 + (lid & 15)) * 144
                                        + (uint32_t)(lid >> 4) * 16;
            const __nv_bfloat16* bb = &Bs[slot][0];
            #pragma unroll
            for (int ks = 0; ks < 4; ks++) {
                uint32_t a0[4];
                ldsm4(a0, arow + ks * 32);
                const uint2 bc = *(const uint2*)(bb + ((ks * 8 + wn) * 32 + lid) * 4);
                const uint2 bh = *(const uint2*)(bb + ((ks * 8 + wn) * 32 + lid) * 4 + 512);
                mma16(cacc, a0, bc.x, bc.y);
                mma16(hacc, a0, bh.x, bh.y);
            }
        }
        __syncthreads();
    }

    const int r0 = m0 + wm * 16 + lr;
    const int c0 = j0 + wn * 8 + lc * 2;
    #pragma unroll
    for (int e = 0; e < 4; e++) {
        int r = r0 + (e >> 1) * 8;
        int c = c0 + (e & 1);
        if (c < NH) {
            float sp = P[(size_t)r * strideP + c];
            float g  = sigf(cacc[e]);
            float av = actf(hacc[e], act);
            float v  = sp + g * (av - sp);
            OutF[(size_t)r * PK + c] = v;
            OutB[(size_t)r * PK + c] = __float2bfloat16_rn(v);
        }
    }
}

__global__ __launch_bounds__(256) void gemm0_kernel() {
    extern __shared__ char smem[];
    auto As = reinterpret_cast<__nv_bfloat16 (*)[32][72]>(smem);
    auto Bs = reinterpret_cast<__nv_bfloat16 (*)[BLK_HALFS]>(smem + A_RING4_BYTES);
    gemm_core32(As, Bs, g_xh, PK0,
                g_w0t + (size_t)blockIdx.x * NKT_0 * BLK_HALFS,
                g_hfp, NH, g_statesF[0], g_statesB[0],
                0, NKT_0, blockIdx.y * 32, blockIdx.x * 32);
}
__global__ __launch_bounds__(256) void edge_kernel(int e0, int e1, int e2) {
    extern __shared__ char smem[];
    auto As = reinterpret_cast<__nv_bfloat16 (*)[32][72]>(smem);
    auto Bs = reinterpret_cast<__nv_bfloat16 (*)[BLK_HALFS]>(smem + A_RING4_BYTES);
    int e = (blockIdx.z == 0) ? e0 : ((blockIdx.z == 1) ? e1 : e2);
    Edge E = c_edges[e];
    gemm_core32(As, Bs, g_statesB[E.pred], PK,
                g_wet[E.w] + (size_t)blockIdx.x * NKT_E * BLK_HALFS,
                g_statesF[E.pred], PK, g_statesF[E.out], g_statesB[E.out],
                E.act, NKT_E, blockIdx.y * 32, blockIdx.x * 32);
}

// ---------------- Fused level-2: edges 1,2,3 all share A = s1 ----------------
// 3-slot ring, one substage per group, loads AFTER the barrier (WAR-safe),
// one ldsm4 feeds all three edges' MMAs.
__global__ __launch_bounds__(256) void lvl2_kernel() {
    extern __shared__ char smem[];
    auto As = reinterpret_cast<__nv_bfloat16 (*)[32][72]>(smem);
    auto Bs = reinterpret_cast<__nv_bfloat16 (*)[3][BLK_HALFS]>(smem + 3 * A_SLOT_BYTES);

    const int tid = threadIdx.x, wid = tid >> 5, lid = tid & 31;
    const int wm = wid & 1, wn = wid >> 1;
    const int lr = lid >> 2, lc = lid & 3;
    const int nt = blockIdx.x, m0 = blockIdx.y * 32, j0 = nt * 32;

    const __nv_bfloat16* A = g_statesB[1];
    const __nv_bfloat16* W[3] = {
        g_wet[1] + (size_t)nt * NKT_E * BLK_HALFS,
        g_wet[2] + (size_t)nt * NKT_E * BLK_HALFS,
        g_wet[3] + (size_t)nt * NKT_E * BLK_HALFS,
    };

    float cacc[3][4] = {}, hacc[3][4] = {};

    auto loadsub = [&](int slot, int kt) {
        {
            int r = tid >> 3, c = tid & 7;
            cp16(&As[slot][r][c * 8], A + (size_t)(m0 + r) * PK + kt * 64 + c * 8);
        }
        #pragma unroll
        for (int e = 0; e < 3; e++) {
            #pragma unroll
            for (int i = 0; i < 2; i++) {
                int idx = tid + i * 256;
                cp16(&Bs[slot][e][idx * 8], W[e] + (size_t)kt * BLK_HALFS + idx * 8);
            }
        }
        cp_commit();
    };

    loadsub(0, 0);
    loadsub(1, 1);

    for (int it = 0; it < NKT_E; it++) {
        if (it + 1 < NKT_E) cp_wait<1>();
        else                cp_wait<0>();
        __syncthreads();
        if (it + 2 < NKT_E) loadsub((it + 2) % 3, it + 2);   // after barrier: WAR-safe

        const int slot = it % 3;
        const uint32_t abase = (uint32_t)__cvta_generic_to_shared(&As[slot][0][0]);
        const uint32_t arow = abase + (uint32_t)(wm * 16 + (lid & 15)) * 144
                                    + (uint32_t)(lid >> 4) * 16;
        #pragma unroll
        for (int ks = 0; ks < 4; ks++) {
            uint32_t a0[4];
            ldsm4(a0, arow + ks * 32);
            const int boff = ((ks * 8 + wn) * 32 + lid) * 4;
            #pragma unroll
            for (int e = 0; e < 3; e++) {
                const __nv_bfloat16* bb = &Bs[slot][e][0];
                const uint2 bc = *(const uint2*)(bb + boff);
                const uint2 bh = *(const uint2*)(bb + boff + 512);
                mma16(cacc[e], a0, bc.x, bc.y);
                mma16(hacc[e], a0, bh.x, bh.y);
            }
        }
    }

    // epilogue: shared pred s1; outs s2(relu), s3(relu), s4(identity)
    const int r0 = m0 + wm * 16 + lr;
    const int c0 = j0 + wn * 8 + lc * 2;
    #pragma unroll
    for (int q = 0; q < 4; q++) {
        int r = r0 + (q >> 1) * 8;
        int c = c0 + (q & 1);
        if (c < NH) {
            float sp = g_statesF[1][(size_t)r * PK + c];
            #pragma unroll
            for (int e = 0; e < 3; e++) {
                const int act = (e < 2) ? 1 : 3;    // e1,e2: relu; e3: identity
                float g  = sigf(cacc[e][q]);
                float av = actf(hacc[e][q], act);
                float v  = sp + g * (av - sp);
                g_statesF[2 + e][(size_t)r * PK + c] = v;
                g_statesB[2 + e][(size_t)r * PK + c] = __float2bfloat16_rn(v);
            }
        }
    }
}

// ---------------- Fused level-4: e5 (sigmoid) + e7 (relu) from s5, + mean + staging ----
__global__ __launch_bounds__(256) void lvl4_kernel(
    const float* __restrict__ inputs, float* __restrict__ out, int t)
{
    extern __shared__ char smem[];
    auto As = reinterpret_cast<__nv_bfloat16 (*)[32][72]>(smem);
    auto Bs = reinterpret_cast<__nv_bfloat16 (*)[2][BLK_HALFS]>(smem + A_RING4_BYTES);

    const int tid = threadIdx.x, wid = tid >> 5, lid = tid & 31;
    const int wm = wid & 1, wn = wid >> 1;
    const int lr = lid >> 2, lc = lid & 3;
    const int nt = blockIdx.x, m0 = blockIdx.y * 32, j0 = nt * 32;

    const __nv_bfloat16* A  = g_statesB[5];
    const __nv_bfloat16* W5 = g_wet[5] + (size_t)nt * NKT_E * BLK_HALFS;
    const __nv_bfloat16* W7 = g_wet[7] + (size_t)nt * NKT_E * BLK_HALFS;

    float c5a[4] = {}, h5a[4] = {}, c7a[4] = {}, h7a[4] = {};

    auto loadsub = [&](int slot, int kt) {
        {
            int r = tid >> 3, c = tid & 7;
            cp16(&As[slot][r][c * 8], A + (size_t)(m0 + r) * PK + kt * 64 + c * 8);
        }
        #pragma unroll
        for (int i = 0; i < 2; i++) {
            int idx = tid + i * 256;
            cp16(&Bs[slot][0][idx * 8], W5 + (size_t)kt * BLK_HALFS + idx * 8);
            cp16(&Bs[slot][1][idx * 8], W7 + (size_t)kt * BLK_HALFS + idx * 8);
        }
    };

    loadsub(0, 0);
    loadsub(1, 1);
    cp_commit();

    const int niter = NKT_E >> 1;
    for (int it = 0; it < niter; it++) {
        if (it + 1 < niter) {
            const int k2 = 2 * it + 2;
            loadsub(k2 & 3, k2);
            loadsub((k2 + 1) & 3, k2 + 1);
            cp_commit();
            cp_wait<1>();
        } else {
            cp_wait<0>();
        }
        __syncthreads();

        #pragma unroll
        for (int half = 0; half < 2; half++) {
            const int slot = (2 * it + half) & 3;
            const uint32_t abase = (uint32_t)__cvta_generic_to_shared(&As[slot][0][0]);
            const uint32_t arow = abase + (uint32_t)(wm * 16 + (lid & 15)) * 144
                                        + (uint32_t)(lid >> 4) * 16;
            const __nv_bfloat16* b5 = &Bs[slot][0][0];
            const __nv_bfloat16* b7 = &Bs[slot][1][0];
            #pragma unroll
            for (int ks = 0; ks < 4; ks++) {
                uint32_t a0[4];
                ldsm4(a0, arow + ks * 32);
                const int boff = ((ks * 8 + wn) * 32 + lid) * 4;
                const uint2 bc5 = *(const uint2*)(b5 + boff);
                const uint2 bh5 = *(const uint2*)(b5 + boff + 512);
                const uint2 bc7 = *(const uint2*)(b7 + boff);
                const uint2 bh7 = *(const uint2*)(b7 + boff + 512);
                mma16(c5a, a0, bc5.x, bc5.y);
                mma16(h5a, a0, bh5.x, bh5.y);
                mma16(c7a, a0, bc7.x, bc7.y);
                mma16(h7a, a0, bh7.x, bh7.y);
            }
        }
        __syncthreads();
    }

    // epilogue: s6/s8 in registers, mean in original s1..s8 order, staging
    const int r0 = m0 + wm * 16 + lr;
    const int c0 = j0 + wn * 8 + lc * 2;
    #pragma unroll
    for (int e = 0; e < 4; e++) {
        int r = r0 + (e >> 1) * 8;
        int c = c0 + (e & 1);
        if (c < NH) {
            float sp = g_statesF[5][(size_t)r * PK + c];
            float v6 = sp + sigf(c5a[e]) * (sigf(h5a[e]) - sp);          // edge5: sigmoid
            float v8 = sp + sigf(c7a[e]) * (fmaxf(h7a[e], 0.f) - sp);    // edge7: relu
            float s = 0.f;
            s += g_statesF[1][(size_t)r * PK + c];
            s += g_statesF[2][(size_t)r * PK + c];
            s += g_statesF[3][(size_t)r * PK + c];
            s += g_statesF[4][(size_t)r * PK + c];
            s += sp;        // s5
            s += v6;        // s6
            s += g_statesF[7][(size_t)r * PK + c];
            s += v8;        // s8
            s *= 0.125f;
            const size_t oi = (size_t)r * NH + c;
            out[(size_t)t * (BB * NH) + oi] = s;
            g_hfp[oi] = s;
            g_xh[(size_t)r * PK0 + PK + c] = __float2bfloat16_rn(s);
            if (t + 1 < TT)
                g_xh[(size_t)r * PK0 + c] =
                    __float2bfloat16_rn(inputs[(size_t)(t + 1) * (BB * NH) + oi]);
            else
                out[(size_t)TT * (BB * NH) + oi] = s;    // hiddens[-1]
        }
    }
}

// ---------------- Initial staging ----------------
__global__ void stage0_kernel(const float* __restrict__ x0, const float* __restrict__ h0) {
    int i = blockIdx.x * blockDim.x + threadIdx.x;
    if (i < BB * NH) {
        int b = i / NH, j = i % NH;
        g_xh[b * PK0 + j]      = __float2bfloat16_rn(x0[i]);
        g_xh[b * PK0 + PK + j] = __float2bfloat16_rn(h0[i]);
        g_hfp[i] = h0[i];
    }
}

// ---------------- Weight prep: packed B fragment blocks (unchanged layout) ----------------
__global__ void prep_w0(const float* __restrict__ W0) {
    size_t i = (size_t)blockIdx.x * blockDim.x + threadIdx.x;
    if (i >= (size_t)NTIL_N * NKT_0 * BLK_HALFS) return;
    int blk = (int)(i >> 12), pos = (int)(i & 4095);
    int nt = blk / NKT_0, kt = blk % NKT_0;
    int hh = pos & 1, rr = (pos >> 1) & 1, lane = (pos >> 2) & 31;
    int g = (pos >> 7) & 7, ks = (pos >> 10) & 3;
    int lcc = lane & 3, lrr = lane >> 2;
    int p = kt * 64 + ks * 16 + 2 * lcc + 8 * rr + hh;
    int kr = (p < NH) ? p : ((p >= PK && p < PK + NH) ? (NH + p - PK) : -1);
    int jj = nt * 32 + (g & 3) * 8 + lrr;
    float v = 0.f;
    if (kr >= 0 && jj < NH) {
        int wc = (g < 4) ? jj : NH + jj;
        v = W0[(size_t)kr * (2 * NH) + wc];
    }
    g_w0t[i] = __float2bfloat16_rn(v);
}
__global__ void prep_we(const float* __restrict__ Ws) {
    size_t i = (size_t)blockIdx.x * blockDim.x + threadIdx.x;
    if (i >= (size_t)8 * NTIL_N * NKT_E * BLK_HALFS) return;
    int e = (int)(i / ((size_t)NTIL_N * NKT_E * BLK_HALFS));
    size_t rm = i % ((size_t)NTIL_N * NKT_E * BLK_HALFS);
    int blk = (int)(rm >> 12), pos = (int)(rm & 4095);
    int nt = blk / NKT_E, kt = blk % NKT_E;
    int hh = pos & 1, rr = (pos >> 1) & 1, lane = (pos >> 2) & 31;
    int g = (pos >> 7) & 7, ks = (pos >> 10) & 3;
    int lcc = lane & 3, lrr = lane >> 2;
    int p = kt * 64 + ks * 16 + 2 * lcc + 8 * rr + hh;
    int jj = nt * 32 + (g & 3) * 8 + lrr;
    float v = 0.f;
    if (p < NH && jj < NH) {
        int wc = (g < 4) ? jj : NH + jj;
        v = Ws[((size_t)e * NH + p) * (2 * NH) + wc];
    }
    g_wet[e][rm] = __float2bfloat16_rn(v);
}

// ---------------- Zero bf16 padding ----------------
__global__ void zero_kernel() {
    int i = blockIdx.x * blockDim.x + threadIdx.x;
    if (i < 9 * BB * PK) (&g_statesB[0][0])[i] = __float2bfloat16_rn(0.f);
    if (i < BB * PK0)    g_xh[i] = __float2bfloat16_rn(0.f);
}

// ---------------- Host ----------------
extern "C" void kernel_launch(void* const* d_in, const int* in_sizes, int n_in,
                              void* d_out, int out_size)
{
    const float* inputs = (const float*)d_in[0];  // [T, B, NH]
    const float* hidden = (const float*)d_in[1];  // [1, B, NH]
    const float* W0     = (const float*)d_in[2];  // [2*NH, 2*NH]
    const float* Ws     = (const float*)d_in[3];  // [8, NH, 2*NH]
    float* out = (float*)d_out;

    cudaFuncSetAttribute(gemm0_kernel, cudaFuncAttributeMaxDynamicSharedMemorySize, SMEM_GEMM);
    cudaFuncSetAttribute(edge_kernel,  cudaFuncAttributeMaxDynamicSharedMemorySize, SMEM_GEMM);
    cudaFuncSetAttribute(lvl2_kernel,  cudaFuncAttributeMaxDynamicSharedMemorySize, SMEM_LVL2);
    cudaFuncSetAttribute(lvl4_kernel,  cudaFuncAttributeMaxDynamicSharedMemorySize, SMEM_LVL4);

    zero_kernel<<<(9 * BB * PK + 255) / 256, 256>>>();
    prep_w0<<<(int)(((size_t)NTIL_N * NKT_0 * BLK_HALFS + 255) / 256), 256>>>(W0);
    prep_we<<<(int)(((size_t)8 * NTIL_N * NKT_E * BLK_HALFS + 255) / 256), 256>>>(Ws);
    stage0_kernel<<<(BB * NH + 255) / 256, 256>>>(inputs, hidden);

    const dim3 blk(256);
    for (int t = 0; t < TT; t++) {
        gemm0_kernel<<<dim3(NTIL_N, 8, 1), blk, SMEM_GEMM>>>();
        edge_kernel<<<dim3(NTIL_N, 8, 1), blk, SMEM_GEMM>>>(0, 0, 0);   // L1: e0
        lvl2_kernel<<<dim3(NTIL_N, 8, 1), blk, SMEM_LVL2>>>();          // L2: e1+e2+e3 fused
        edge_kernel<<<dim3(NTIL_N, 8, 2), blk, SMEM_GEMM>>>(4, 6, 0);   // L3
        lvl4_kernel<<<dim3(NTIL_N, 8, 1), blk, SMEM_LVL4>>>(inputs, out, t);  // L4 + mean + staging
    }
}